// round 3
// baseline (speedup 1.0000x reference)
#include <cuda_runtime.h>

#define NB    4
#define NSEQ  2048
#define DIMV  512
#define NH    8
#define HD    64
#define NM    4
#define NROWS 16     // NB*NM
#define HM    32     // NH*NM
#define ASCALE 0.125f

// ---------------- scratch (device globals; no allocation allowed) ----------------
__device__ float g_q[NROWS * DIMV];          // q rows (b*4+m) x 512
__device__ float g_qk[NB * HM * DIMV];       // [b][h*4+m][dcol]
__device__ float g_dots[NB * HM * NSEQ];     // dots, then attn in-place
__device__ float g_part[NB * 16 * HM * DIMV];// split-n partials of attn@x
__device__ float g_ax[NB * HM * DIMV];       // reduced attn@x
__device__ float g_y[NROWS * DIMV];          // per-head V-projected, concat

typedef unsigned long long u64;

__device__ __forceinline__ u64 fma2(u64 a, u64 b, u64 c) {
    u64 d; asm("fma.rn.f32x2 %0, %1, %2, %3;" : "=l"(d) : "l"(a), "l"(b), "l"(c)); return d;
}
__device__ __forceinline__ u64 pack2(float x, float y) {
    u64 r; asm("mov.b64 %0, {%1, %2};" : "=l"(r) : "f"(x), "f"(y)); return r;
}
__device__ __forceinline__ float2 unpack2(u64 v) {
    float2 f; asm("mov.b64 {%0, %1}, %2;" : "=f"(f.x), "=f"(f.y) : "l"(v)); return f;
}

// ---------------- K1: q = x[:, 0:4] @ Wq  (16x512, k=512) ----------------
// grid 64 (8 cols/block), 256 thr = 8 c x 32 k-groups, smem split-k reduce.
__global__ void k1_q(const float* __restrict__ x, const float* __restrict__ Wq) {
    __shared__ float A[NROWS * DIMV];
    int t = threadIdx.x;
    int c0 = blockIdx.x * 8;
    for (int i = t; i < NROWS * DIMV; i += 256) {
        int r = i >> 9, k = i & 511;
        A[i] = x[(((r >> 2) * NSEQ) + (r & 3)) * DIMV + k];
    }
    __syncthreads();
    int cl = t & 7, kg = t >> 3;
    int c = c0 + cl;
    float acc[NROWS];
#pragma unroll
    for (int r = 0; r < NROWS; r++) acc[r] = 0.f;
    int k0 = kg << 4;
#pragma unroll
    for (int i = 0; i < 16; i++) {
        float w = Wq[(k0 + i) * DIMV + c];
#pragma unroll
        for (int r = 0; r < NROWS; r++) acc[r] += A[r * DIMV + k0 + i] * w;
    }
    __syncthreads();                 // done reading A; reuse it for reduction
#pragma unroll
    for (int r = 0; r < NROWS; r++) A[(kg << 7) + (r << 3) + cl] = acc[r];
    __syncthreads();
    if (t < 128) {
        int r = t >> 3, c2 = t & 7;
        float s = 0.f;
#pragma unroll
        for (int kg2 = 0; kg2 < 32; kg2++) s += A[(kg2 << 7) + (r << 3) + c2];
        g_q[r * DIMV + c0 + c2] = s;
    }
}

// ---------------- K2: qk[b,h,m,dcol] = sum_dd q[b,m,h*64+dd] * Wk[dcol, h*64+dd] ----------------
// Wk = Wkv[:, :512] (row stride 1024). grid 256 x 256, one output/thread, k=64, float4.
__global__ void k2_qk(const float* __restrict__ Wkv) {
    int idx = blockIdx.x * 256 + threadIdx.x;   // 65536
    int dcol = idx & 511;
    int rem = idx >> 9;
    int hm = rem & 31, b = rem >> 5;
    int h = hm >> 2, m = hm & 3;
    const float4* qrow = (const float4*)(g_q + ((b << 2) + m) * DIMV + h * HD);
    const float4* wrow = (const float4*)(Wkv + (size_t)dcol * (2 * DIMV) + h * HD);
    float acc = 0.f;
#pragma unroll
    for (int dd = 0; dd < HD / 4; dd++) {
        float4 a = qrow[dd], w = wrow[dd];
        acc += a.x * w.x + a.y * w.y + a.z * w.z + a.w * w.w;
    }
    g_qk[idx] = acc;
}

// ---------------- K3: dots = qk @ x^T * SCALE + bias[:,:,0:4,:] ----------------
// grid 128 = (b, n-chunk 64). (32 x 512) @ (512 x 64) with f32x2 packed FMA.
__global__ void k3_dots(const float* __restrict__ x, const float* __restrict__ bias) {
    __shared__ float QKs[64][34];
    __shared__ float Xs[64][68];
    int t = threadIdx.x;
    int b = blockIdx.x >> 5, nb = blockIdx.x & 31;
    int n0 = nb << 6;
    int tn = t & 15, th = t >> 4;
    int n4 = tn << 2, hm2 = th << 1;
    u64 acc[2][2];
#pragma unroll
    for (int j = 0; j < 2; j++) { acc[j][0] = pack2(0.f, 0.f); acc[j][1] = pack2(0.f, 0.f); }
    for (int dt = 0; dt < 8; dt++) {
        int d0 = dt << 6;
        {   // QK tile 64kk x 32hm (transposed store)
            int hm = t >> 3, q8 = t & 7;
#pragma unroll
            for (int i = 0; i < 2; i++) {
                int kk = (q8 + (i << 3)) << 2;
                float4 v = *(const float4*)&g_qk[(b * HM + hm) * DIMV + d0 + kk];
                QKs[kk][hm] = v.x; QKs[kk + 1][hm] = v.y; QKs[kk + 2][hm] = v.z; QKs[kk + 3][hm] = v.w;
            }
            // X tile 64kk x 64n (transposed store)
            int nn = t >> 2, q4 = t & 3;
#pragma unroll
            for (int i = 0; i < 4; i++) {
                int kk = (q4 + (i << 2)) << 2;
                float4 v = *(const float4*)&x[(size_t)(b * NSEQ + n0 + nn) * DIMV + d0 + kk];
                Xs[kk][nn] = v.x; Xs[kk + 1][nn] = v.y; Xs[kk + 2][nn] = v.z; Xs[kk + 3][nn] = v.w;
            }
        }
        __syncthreads();
#pragma unroll
        for (int kk = 0; kk < 64; kk++) {
            float2 a = *(const float2*)&QKs[kk][hm2];
            ulonglong2 xx = *(const ulonglong2*)&Xs[kk][n4];
            u64 a0 = pack2(a.x, a.x), a1 = pack2(a.y, a.y);
            acc[0][0] = fma2(a0, xx.x, acc[0][0]);
            acc[0][1] = fma2(a0, xx.y, acc[0][1]);
            acc[1][0] = fma2(a1, xx.x, acc[1][0]);
            acc[1][1] = fma2(a1, xx.y, acc[1][1]);
        }
        __syncthreads();
    }
#pragma unroll
    for (int j = 0; j < 2; j++) {
        int hm = hm2 + j;
        int h = hm >> 2, m = hm & 3;
        float4 bv = *(const float4*)&bias[(size_t)((b * NH + h) * NSEQ + m) * NSEQ + n0 + n4];
        float2 p0 = unpack2(acc[j][0]);
        float2 p1 = unpack2(acc[j][1]);
        float4 o = make_float4(p0.x * ASCALE + bv.x, p0.y * ASCALE + bv.y,
                               p1.x * ASCALE + bv.z, p1.y * ASCALE + bv.w);
        *(float4*)&g_dots[(b * HM + hm) * NSEQ + n0 + n4] = o;
    }
}

// ---------------- K4: row softmax over N=2048 (128 rows), in place ----------------
__global__ void k4_softmax() {
    __shared__ float sred[8];
    int row = blockIdx.x, t = threadIdx.x;
    float* p = g_dots + row * NSEQ;
    float v[8];
    float mx = -3.4e38f;
#pragma unroll
    for (int i = 0; i < 8; i++) { v[i] = p[t + (i << 8)]; mx = fmaxf(mx, v[i]); }
#pragma unroll
    for (int o = 16; o; o >>= 1) mx = fmaxf(mx, __shfl_xor_sync(0xffffffffu, mx, o));
    if ((t & 31) == 0) sred[t >> 5] = mx;
    __syncthreads();
    float bm = sred[0];
#pragma unroll
    for (int w = 1; w < 8; w++) bm = fmaxf(bm, sred[w]);
    __syncthreads();
    float s = 0.f;
#pragma unroll
    for (int i = 0; i < 8; i++) { v[i] = __expf(v[i] - bm); s += v[i]; }
#pragma unroll
    for (int o = 16; o; o >>= 1) s += __shfl_xor_sync(0xffffffffu, s, o);
    if ((t & 31) == 0) sred[t >> 5] = s;
    __syncthreads();
    float tot = 0.f;
#pragma unroll
    for (int w = 0; w < 8; w++) tot += sred[w];
    float inv = 1.f / tot;
#pragma unroll
    for (int i = 0; i < 8; i++) p[t + (i << 8)] = v[i] * inv;
}

// ---------------- K5: partial ax = attn_chunk @ x_chunk ----------------
// grid 128 = (b, n-chunk 16, d-half 2). (32 x 128) @ (128 x 256). f32x2 FMA.
__global__ void k5_part(const float* __restrict__ x) {
    __shared__ float As[32][36];
    __shared__ float Xs[32][128];
    int t = threadIdx.x;
    int b = blockIdx.x >> 5;
    int rest = blockIdx.x & 31;
    int c = rest >> 1, dh = rest & 1;
    int n0 = c << 7;
    int td = t & 31, thm = t >> 5;
    int hm4 = thm << 2;
    for (int dt = 0; dt < 2; dt++) {
        int d0 = (dh << 8) + (dt << 7);
        u64 acc[4][2];
#pragma unroll
        for (int j = 0; j < 4; j++) { acc[j][0] = pack2(0.f, 0.f); acc[j][1] = pack2(0.f, 0.f); }
        for (int nt = 0; nt < 4; nt++) {
            int nbase = n0 + (nt << 5);
            {   // attn tile 32n x 32hm (transposed)
                int hm = t >> 3;
                int nn = (t & 7) << 2;
                float4 v = *(const float4*)&g_dots[(b * HM + hm) * NSEQ + nbase + nn];
                As[nn][hm] = v.x; As[nn + 1][hm] = v.y; As[nn + 2][hm] = v.z; As[nn + 3][hm] = v.w;
            }
            {   // x tile 32n x 128d (natural)
                int nn = t >> 3, q8 = t & 7;
#pragma unroll
                for (int i = 0; i < 4; i++) {
                    int dd = (q8 + (i << 3)) << 2;
                    *(float4*)&Xs[nn][dd] =
                        *(const float4*)&x[(size_t)(b * NSEQ + nbase + nn) * DIMV + d0 + dd];
                }
            }
            __syncthreads();
#pragma unroll
            for (int nn = 0; nn < 32; nn++) {
                float4 a = *(const float4*)&As[nn][hm4];
                ulonglong2 xx = *(const ulonglong2*)&Xs[nn][td << 2];
                u64 a0 = pack2(a.x, a.x), a1 = pack2(a.y, a.y);
                u64 a2 = pack2(a.z, a.z), a3 = pack2(a.w, a.w);
                acc[0][0] = fma2(a0, xx.x, acc[0][0]); acc[0][1] = fma2(a0, xx.y, acc[0][1]);
                acc[1][0] = fma2(a1, xx.x, acc[1][0]); acc[1][1] = fma2(a1, xx.y, acc[1][1]);
                acc[2][0] = fma2(a2, xx.x, acc[2][0]); acc[2][1] = fma2(a2, xx.y, acc[2][1]);
                acc[3][0] = fma2(a3, xx.x, acc[3][0]); acc[3][1] = fma2(a3, xx.y, acc[3][1]);
            }
            __syncthreads();
        }
#pragma unroll
        for (int j = 0; j < 4; j++) {
            float2 p0 = unpack2(acc[j][0]), p1 = unpack2(acc[j][1]);
            float4 o = make_float4(p0.x, p0.y, p1.x, p1.y);
            *(float4*)&g_part[(size_t)(((b << 4) + c) * HM + hm4 + j) * DIMV + d0 + (td << 2)] = o;
        }
    }
}

// ---------------- K6: reduce 16 n-chunk partials ----------------
__global__ void k6_reduce() {
    int base = blockIdx.x * 1024 + threadIdx.x;
#pragma unroll
    for (int i = 0; i < 4; i++) {
        int idx = base + (i << 8);
        int b = idx >> 14;
        int rest = idx & 16383;
        float s = 0.f;
#pragma unroll
        for (int cc = 0; cc < 16; cc++)
            s += g_part[((b << 4) + cc) * (HM * DIMV) + rest];
        g_ax[idx] = s;
    }
}

// ---------------- K7: y[:, c] = ax_h @ Wv[:, c], h = c/64 ----------------
// Wv = Wkv[:, 512:1024]. Same split-k structure as K1.
__global__ void k7_y(const float* __restrict__ Wkv) {
    __shared__ float A[NROWS * DIMV];
    int t = threadIdx.x;
    int c0 = blockIdx.x * 8;
    int h = c0 >> 6;                 // constant per block (8 | 64)
    for (int i = t; i < NROWS * DIMV; i += 256) {
        int r = i >> 9, k = i & 511;
        A[i] = g_ax[((((r >> 2) * NH + h) * NM) + (r & 3)) * DIMV + k];
    }
    __syncthreads();
    int cl = t & 7, kg = t >> 3;
    int c = c0 + cl;
    float acc[NROWS];
#pragma unroll
    for (int r = 0; r < NROWS; r++) acc[r] = 0.f;
    int k0 = kg << 4;
#pragma unroll
    for (int i = 0; i < 16; i++) {
        float w = Wkv[(size_t)(k0 + i) * (2 * DIMV) + DIMV + c];
#pragma unroll
        for (int r = 0; r < NROWS; r++) acc[r] += A[r * DIMV + k0 + i] * w;
    }
    __syncthreads();
#pragma unroll
    for (int r = 0; r < NROWS; r++) A[(kg << 7) + (r << 3) + cl] = acc[r];
    __syncthreads();
    if (t < 128) {
        int r = t >> 3, c2 = t & 7;
        float s = 0.f;
#pragma unroll
        for (int kg2 = 0; kg2 < 32; kg2++) s += A[(kg2 << 7) + (r << 3) + c2];
        g_y[r * DIMV + c0 + c2] = s;
    }
}

// ---------------- K8: out = y @ Wo + bo ----------------
__global__ void k8_out(const float* __restrict__ Wo, const float* __restrict__ bo,
                       float* __restrict__ out) {
    __shared__ float A[NROWS * DIMV];
    int t = threadIdx.x;
    int c0 = blockIdx.x * 8;
    for (int i = t; i < NROWS * DIMV; i += 256) A[i] = g_y[i];
    __syncthreads();
    int cl = t & 7, kg = t >> 3;
    int c = c0 + cl;
    float acc[NROWS];
#pragma unroll
    for (int r = 0; r < NROWS; r++) acc[r] = 0.f;
    int k0 = kg << 4;
#pragma unroll
    for (int i = 0; i < 16; i++) {
        float w = Wo[(k0 + i) * DIMV + c];
#pragma unroll
        for (int r = 0; r < NROWS; r++) acc[r] += A[r * DIMV + k0 + i] * w;
    }
    __syncthreads();
#pragma unroll
    for (int r = 0; r < NROWS; r++) A[(kg << 7) + (r << 3) + cl] = acc[r];
    __syncthreads();
    if (t < 128) {
        int r = t >> 3, c2 = t & 7;
        float s = 0.f;
#pragma unroll
        for (int kg2 = 0; kg2 < 32; kg2++) s += A[(kg2 << 7) + (r << 3) + c2];
        out[r * DIMV + c0 + c2] = s + bo[c0 + c2];
    }
}

// ---------------- launch ----------------
extern "C" void kernel_launch(void* const* d_in, const int* in_sizes, int n_in,
                              void* d_out, int out_size) {
    const float* x    = (const float*)d_in[0];   // (4, 2048, 512)
    const float* bias = (const float*)d_in[1];   // (4, 8, 2048, 2048)
    const float* Wq   = (const float*)d_in[2];   // (512, 512)
    const float* Wkv  = (const float*)d_in[3];   // (512, 1024)
    const float* Wo   = (const float*)d_in[4];   // (512, 512)
    const float* bo   = (const float*)d_in[5];   // (512,)
    float* out = (float*)d_out;                  // (4, 4, 512)

    k1_q<<<64, 256>>>(x, Wq);
    k2_qk<<<256, 256>>>(Wkv);
    k3_dots<<<128, 256>>>(x, bias);
    k4_softmax<<<128, 256>>>();
    k5_part<<<128, 256>>>(x);
    k6_reduce<<<64, 256>>>();
    k7_y<<<64, 256>>>(Wkv);
    k8_out<<<64, 256>>>(Wo, bo, out);
}

// round 4
// speedup vs baseline: 1.0752x; 1.0752x over previous
#include <cuda_runtime.h>

#define NB    4
#define NSEQ  2048
#define DIMV  512
#define NH    8
#define HD    64
#define NM    4
#define NROWS 16     // NB*NM
#define HM    32     // NH*NM
#define ASCALE 0.125f

// ---------------- scratch (device globals; no allocation allowed) ----------------
__device__ float g_q[NROWS * DIMV];          // q rows (b*4+m) x 512
__device__ float g_qk[NB * HM * DIMV];       // [b][h*4+m][kin]
__device__ float g_dots[NB * HM * NSEQ];     // raw dots (scaled + bias)
__device__ float g_smax[NB * HM * 32];       // per-(row, 64-chunk) max
__device__ float g_ssum[NB * HM * 32];       // per-(row, 64-chunk) sum exp(v - chunkmax)
__device__ float g_ax[NB * HM * DIMV];       // attn@x accumulator (REDG target)
__device__ float g_y[NROWS * DIMV];          // per-head V-projected, concat

typedef unsigned long long u64;

__device__ __forceinline__ u64 fma2(u64 a, u64 b, u64 c) {
    u64 d; asm("fma.rn.f32x2 %0, %1, %2, %3;" : "=l"(d) : "l"(a), "l"(b), "l"(c)); return d;
}
__device__ __forceinline__ u64 pack2(float x, float y) {
    u64 r; asm("mov.b64 %0, {%1, %2};" : "=l"(r) : "f"(x), "f"(y)); return r;
}
__device__ __forceinline__ float2 unpack2(u64 v) {
    float2 f; asm("mov.b64 {%0, %1}, %2;" : "=f"(f.x), "=f"(f.y) : "l"(v)); return f;
}
__device__ __forceinline__ void redg4(float* p, float4 v) {
    asm volatile("red.global.add.v4.f32 [%0], {%1, %2, %3, %4};"
                 :: "l"(p), "f"(v.x), "f"(v.y), "f"(v.z), "f"(v.w) : "memory");
}

// ---------------- K1: q = x[:, 0:4] @ Wq  (16x512, k=512) ----------------
// grid 64 (8 cols/block), 256 thr = 8 c x 32 k-groups, smem split-k reduce.
__global__ void k1_q(const float* __restrict__ x, const float* __restrict__ Wq) {
    __shared__ float A[NROWS * DIMV];
    int t = threadIdx.x;
    int c0 = blockIdx.x * 8;
    for (int i = t; i < NROWS * DIMV / 4; i += 256) {
        int r = i >> 7, k = (i & 127) << 2;
        *(float4*)&A[r * DIMV + k] =
            *(const float4*)&x[(size_t)(((r >> 2) * NSEQ) + (r & 3)) * DIMV + k];
    }
    __syncthreads();
    int cl = t & 7, kg = t >> 3;
    int c = c0 + cl;
    float acc[NROWS];
#pragma unroll
    for (int r = 0; r < NROWS; r++) acc[r] = 0.f;
    int k0 = kg << 4;
#pragma unroll
    for (int i = 0; i < 16; i++) {
        float w = Wq[(k0 + i) * DIMV + c];
#pragma unroll
        for (int r = 0; r < NROWS; r++) acc[r] += A[r * DIMV + k0 + i] * w;
    }
    __syncthreads();                 // done reading A; reuse it for reduction
#pragma unroll
    for (int r = 0; r < NROWS; r++) A[(kg << 7) + (r << 3) + cl] = acc[r];
    __syncthreads();
    if (t < 128) {
        int r = t >> 3, c2 = t & 7;
        float s = 0.f;
#pragma unroll
        for (int kg2 = 0; kg2 < 32; kg2++) s += A[(kg2 << 7) + (r << 3) + c2];
        g_q[r * DIMV + c0 + c2] = s;
    }
}

// ---------------- K2: qk[b,h,m,kin] = sum_dd q[b,m,h*64+dd] * Wkv[kin, h*64+dd] ----------------
// grid 128 = (8 h x 16 kin-chunks of 32). Wkv read once, coalesced, smem-tiled.
// Also zeroes g_ax for K5's REDG accumulation.
__global__ void k2_qk(const float* __restrict__ Wkv) {
    __shared__ float Ws[32][68];   // kin x dd (padded)
    __shared__ float Qs[16][68];   // bm  x dd (padded)
    int t = threadIdx.x;
    int h = blockIdx.x >> 4, kc = blockIdx.x & 15;
    int kin0 = kc << 5;
    // W tile: 32 rows x 64 floats (512 float4, 2/thread), coalesced per row
#pragma unroll
    for (int i = 0; i < 2; i++) {
        int idx = t + (i << 8);
        int r = idx >> 4, c = (idx & 15) << 2;
        *(float4*)&Ws[r][c] =
            *(const float4*)&Wkv[(size_t)(kin0 + r) * (2 * DIMV) + h * HD + c];
    }
    // q tile: 16 rows x 64 floats (256 float4, 1/thread)
    {
        int r = t >> 4, c = (t & 15) << 2;
        *(float4*)&Qs[r][c] = *(const float4*)&g_q[r * DIMV + h * HD + c];
    }
    __syncthreads();
    int bm = t >> 4, kin = t & 15;
    float acc0 = 0.f, acc1 = 0.f;
#pragma unroll
    for (int dd = 0; dd < HD; dd += 4) {
        float4 q  = *(const float4*)&Qs[bm][dd];
        float4 w0 = *(const float4*)&Ws[kin][dd];
        float4 w1 = *(const float4*)&Ws[kin + 16][dd];
        acc0 += q.x * w0.x + q.y * w0.y + q.z * w0.z + q.w * w0.w;
        acc1 += q.x * w1.x + q.y * w1.y + q.z * w1.z + q.w * w1.w;
    }
    int b = bm >> 2, m = bm & 3;
    int hm = (h << 2) + m;
    g_qk[(b * HM + hm) * DIMV + kin0 + kin] = acc0;
    g_qk[(b * HM + hm) * DIMV + kin0 + kin + 16] = acc1;
    // zero g_ax (65536 elems, 32768 threads -> 2 each)
    int zi = blockIdx.x * 256 + t;
    g_ax[zi] = 0.f;
    g_ax[zi + 32768] = 0.f;
}

// ---------------- K3: dots = qk @ x^T * SCALE + bias[:,:,0:4,:]  + chunk stats ----------------
// grid 128 = (b, n-chunk 64). (32 x 512) @ (512 x 64) with f32x2 packed FMA.
__global__ void k3_dots(const float* __restrict__ x, const float* __restrict__ bias) {
    __shared__ float QKs[64][34];
    __shared__ float Xs[64][68];
    int t = threadIdx.x;
    int b = blockIdx.x >> 5, nb = blockIdx.x & 31;
    int n0 = nb << 6;
    int tn = t & 15, th = t >> 4;
    int n4 = tn << 2, hm2 = th << 1;
    u64 acc[2][2];
#pragma unroll
    for (int j = 0; j < 2; j++) { acc[j][0] = pack2(0.f, 0.f); acc[j][1] = pack2(0.f, 0.f); }
    for (int dt = 0; dt < 8; dt++) {
        int d0 = dt << 6;
        {   // QK tile 64kk x 32hm (transposed store)
            int hm = t >> 3, q8 = t & 7;
#pragma unroll
            for (int i = 0; i < 2; i++) {
                int kk = (q8 + (i << 3)) << 2;
                float4 v = *(const float4*)&g_qk[(b * HM + hm) * DIMV + d0 + kk];
                QKs[kk][hm] = v.x; QKs[kk + 1][hm] = v.y; QKs[kk + 2][hm] = v.z; QKs[kk + 3][hm] = v.w;
            }
            // X tile 64kk x 64n (transposed store)
            int nn = t >> 2, q4 = t & 3;
#pragma unroll
            for (int i = 0; i < 4; i++) {
                int kk = (q4 + (i << 2)) << 2;
                float4 v = *(const float4*)&x[(size_t)(b * NSEQ + n0 + nn) * DIMV + d0 + kk];
                Xs[kk][nn] = v.x; Xs[kk + 1][nn] = v.y; Xs[kk + 2][nn] = v.z; Xs[kk + 3][nn] = v.w;
            }
        }
        __syncthreads();
#pragma unroll
        for (int kk = 0; kk < 64; kk++) {
            float2 a = *(const float2*)&QKs[kk][hm2];
            ulonglong2 xx = *(const ulonglong2*)&Xs[kk][n4];
            u64 a0 = pack2(a.x, a.x), a1 = pack2(a.y, a.y);
            acc[0][0] = fma2(a0, xx.x, acc[0][0]);
            acc[0][1] = fma2(a0, xx.y, acc[0][1]);
            acc[1][0] = fma2(a1, xx.x, acc[1][0]);
            acc[1][1] = fma2(a1, xx.y, acc[1][1]);
        }
        __syncthreads();
    }
#pragma unroll
    for (int j = 0; j < 2; j++) {
        int hm = hm2 + j;
        int h = hm >> 2, m = hm & 3;
        float4 bv = *(const float4*)&bias[(size_t)((b * NH + h) * NSEQ + m) * NSEQ + n0 + n4];
        float2 p0 = unpack2(acc[j][0]);
        float2 p1 = unpack2(acc[j][1]);
        float4 o = make_float4(p0.x * ASCALE + bv.x, p0.y * ASCALE + bv.y,
                               p1.x * ASCALE + bv.z, p1.y * ASCALE + bv.w);
        *(float4*)&g_dots[(b * HM + hm) * NSEQ + n0 + n4] = o;
        // chunk stats: max + sum(exp(v - max)) over this 64-wide n-chunk (16 tn lanes)
        float M = fmaxf(fmaxf(o.x, o.y), fmaxf(o.z, o.w));
#pragma unroll
        for (int off = 8; off; off >>= 1) M = fmaxf(M, __shfl_xor_sync(0xffffffffu, M, off));
        float s = __expf(o.x - M) + __expf(o.y - M) + __expf(o.z - M) + __expf(o.w - M);
#pragma unroll
        for (int off = 8; off; off >>= 1) s += __shfl_xor_sync(0xffffffffu, s, off);
        if (tn == 0) {
            g_smax[(b * HM + hm) * 32 + nb] = M;
            g_ssum[(b * HM + hm) * 32 + nb] = s;
        }
    }
}

// ---------------- K5: ax += softmax(dots) @ x  (fused softmax-apply + REDG accumulate) ----------------
// grid 128 = (b, n-chunk 16, d-half 2). (32 x 128) @ (128 x 256). f32x2 FMA.
__global__ void k5_part(const float* __restrict__ x) {
    __shared__ float As[32][36];
    __shared__ float Xs[32][128];
    __shared__ float sM[32], sInv[32];
    int t = threadIdx.x;
    int b = blockIdx.x >> 5;
    int rest = blockIdx.x & 31;
    int c = rest >> 1, dh = rest & 1;
    int n0 = c << 7;
    int td = t & 31, thm = t >> 5;
    int hm4 = thm << 2;
    // prologue: combine 32 chunk stats per row -> row max M and 1/S
    {
        int row = t >> 3, j8 = t & 7;
        const float* pm = g_smax + (b * HM + row) * 32 + (j8 << 2);
        const float* ps = g_ssum + (b * HM + row) * 32 + (j8 << 2);
        float mv[4], sv[4];
        float M = -3.4e38f;
#pragma unroll
        for (int i = 0; i < 4; i++) { mv[i] = pm[i]; sv[i] = ps[i]; M = fmaxf(M, mv[i]); }
#pragma unroll
        for (int off = 4; off; off >>= 1) M = fmaxf(M, __shfl_xor_sync(0xffffffffu, M, off));
        float s = 0.f;
#pragma unroll
        for (int i = 0; i < 4; i++) s += __expf(mv[i] - M) * sv[i];
#pragma unroll
        for (int off = 4; off; off >>= 1) s += __shfl_xor_sync(0xffffffffu, s, off);
        if (j8 == 0) { sM[row] = M; sInv[row] = 1.f / s; }
    }
    __syncthreads();
    for (int dt = 0; dt < 2; dt++) {
        int d0 = (dh << 8) + (dt << 7);
        u64 acc[4][2];
#pragma unroll
        for (int j = 0; j < 4; j++) { acc[j][0] = pack2(0.f, 0.f); acc[j][1] = pack2(0.f, 0.f); }
        for (int nt = 0; nt < 4; nt++) {
            int nbase = n0 + (nt << 5);
            {   // attn tile 32n x 32hm (transposed), softmax applied at load
                int hm = t >> 3;
                int nn = (t & 7) << 2;
                float4 v = *(const float4*)&g_dots[(b * HM + hm) * NSEQ + nbase + nn];
                float M = sM[hm], is = sInv[hm];
                As[nn][hm]     = __expf(v.x - M) * is;
                As[nn + 1][hm] = __expf(v.y - M) * is;
                As[nn + 2][hm] = __expf(v.z - M) * is;
                As[nn + 3][hm] = __expf(v.w - M) * is;
            }
            {   // x tile 32n x 128d (natural)
                int nn = t >> 3, q8 = t & 7;
#pragma unroll
                for (int i = 0; i < 4; i++) {
                    int dd = (q8 + (i << 3)) << 2;
                    *(float4*)&Xs[nn][dd] =
                        *(const float4*)&x[(size_t)(b * NSEQ + nbase + nn) * DIMV + d0 + dd];
                }
            }
            __syncthreads();
#pragma unroll
            for (int nn = 0; nn < 32; nn++) {
                float4 a = *(const float4*)&As[nn][hm4];
                ulonglong2 xx = *(const ulonglong2*)&Xs[nn][td << 2];
                u64 a0 = pack2(a.x, a.x), a1 = pack2(a.y, a.y);
                u64 a2 = pack2(a.z, a.z), a3 = pack2(a.w, a.w);
                acc[0][0] = fma2(a0, xx.x, acc[0][0]); acc[0][1] = fma2(a0, xx.y, acc[0][1]);
                acc[1][0] = fma2(a1, xx.x, acc[1][0]); acc[1][1] = fma2(a1, xx.y, acc[1][1]);
                acc[2][0] = fma2(a2, xx.x, acc[2][0]); acc[2][1] = fma2(a2, xx.y, acc[2][1]);
                acc[3][0] = fma2(a3, xx.x, acc[3][0]); acc[3][1] = fma2(a3, xx.y, acc[3][1]);
            }
            __syncthreads();
        }
#pragma unroll
        for (int j = 0; j < 4; j++) {
            float2 p0 = unpack2(acc[j][0]), p1 = unpack2(acc[j][1]);
            redg4(&g_ax[(size_t)(b * HM + hm4 + j) * DIMV + d0 + (td << 2)],
                  make_float4(p0.x, p0.y, p1.x, p1.y));
        }
    }
}

// ---------------- K7: y[:, c] = ax_h @ Wv[:, c], h = c/64 ----------------
// Wv = Wkv[:, 512:1024]. Same split-k structure as K1.
__global__ void k7_y(const float* __restrict__ Wkv) {
    __shared__ float A[NROWS * DIMV];
    int t = threadIdx.x;
    int c0 = blockIdx.x * 8;
    int h = c0 >> 6;                 // constant per block (8 | 64)
    for (int i = t; i < NROWS * DIMV / 4; i += 256) {
        int r = i >> 7, k = (i & 127) << 2;
        *(float4*)&A[r * DIMV + k] =
            *(const float4*)&g_ax[(size_t)((((r >> 2) * NH + h) * NM) + (r & 3)) * DIMV + k];
    }
    __syncthreads();
    int cl = t & 7, kg = t >> 3;
    int c = c0 + cl;
    float acc[NROWS];
#pragma unroll
    for (int r = 0; r < NROWS; r++) acc[r] = 0.f;
    int k0 = kg << 4;
#pragma unroll
    for (int i = 0; i < 16; i++) {
        float w = Wkv[(size_t)(k0 + i) * (2 * DIMV) + DIMV + c];
#pragma unroll
        for (int r = 0; r < NROWS; r++) acc[r] += A[r * DIMV + k0 + i] * w;
    }
    __syncthreads();
#pragma unroll
    for (int r = 0; r < NROWS; r++) A[(kg << 7) + (r << 3) + cl] = acc[r];
    __syncthreads();
    if (t < 128) {
        int r = t >> 3, c2 = t & 7;
        float s = 0.f;
#pragma unroll
        for (int kg2 = 0; kg2 < 32; kg2++) s += A[(kg2 << 7) + (r << 3) + c2];
        g_y[r * DIMV + c0 + c2] = s;
    }
}

// ---------------- K8: out = y @ Wo + bo ----------------
__global__ void k8_out(const float* __restrict__ Wo, const float* __restrict__ bo,
                       float* __restrict__ out) {
    __shared__ float A[NROWS * DIMV];
    int t = threadIdx.x;
    int c0 = blockIdx.x * 8;
    for (int i = t; i < NROWS * DIMV / 4; i += 256)
        *(float4*)&A[i << 2] = *(const float4*)&g_y[i << 2];
    __syncthreads();
    int cl = t & 7, kg = t >> 3;
    int c = c0 + cl;
    float acc[NROWS];
#pragma unroll
    for (int r = 0; r < NROWS; r++) acc[r] = 0.f;
    int k0 = kg << 4;
#pragma unroll
    for (int i = 0; i < 16; i++) {
        float w = Wo[(k0 + i) * DIMV + c];
#pragma unroll
        for (int r = 0; r < NROWS; r++) acc[r] += A[r * DIMV + k0 + i] * w;
    }
    __syncthreads();
#pragma unroll
    for (int r = 0; r < NROWS; r++) A[(kg << 7) + (r << 3) + cl] = acc[r];
    __syncthreads();
    if (t < 128) {
        int r = t >> 3, c2 = t & 7;
        float s = 0.f;
#pragma unroll
        for (int kg2 = 0; kg2 < 32; kg2++) s += A[(kg2 << 7) + (r << 3) + c2];
        out[r * DIMV + c0 + c2] = s + bo[c0 + c2];
    }
}

// ---------------- launch ----------------
extern "C" void kernel_launch(void* const* d_in, const int* in_sizes, int n_in,
                              void* d_out, int out_size) {
    const float* x    = (const float*)d_in[0];   // (4, 2048, 512)
    const float* bias = (const float*)d_in[1];   // (4, 8, 2048, 2048)
    const float* Wq   = (const float*)d_in[2];   // (512, 512)
    const float* Wkv  = (const float*)d_in[3];   // (512, 1024)
    const float* Wo   = (const float*)d_in[4];   // (512, 512)
    const float* bo   = (const float*)d_in[5];   // (512,)
    float* out = (float*)d_out;                  // (4, 4, 512)

    k1_q<<<64, 256>>>(x, Wq);
    k2_qk<<<128, 256>>>(Wkv);
    k3_dots<<<128, 256>>>(x, bias);
    k5_part<<<128, 256>>>(x);
    k7_y<<<64, 256>>>(Wkv);
    k8_out<<<64, 256>>>(Wo, bo, out);
}